// round 2
// baseline (speedup 1.0000x reference)
#include <cuda_runtime.h>
#include <cuda_bf16.h>
#include <cstdint>

// Problem constants
#define HEADS   8
#define DK      64
#define KSIZE   7
#define PAD     3
#define S_LEN   256
#define D_MODEL 512
#define M_ROWS  32768            // B*HW*S = 2*64*256
#define N_QKV   1536             // 3*HEADS*DK
#define K_DIM   512

// Scratch (allocation-free rule: __device__ globals)
__device__ float g_qkv[(size_t)M_ROWS * N_QKV];   // 192 MiB
__device__ float g_att[(size_t)M_ROWS * D_MODEL]; // 64 MiB

// ---------------------------------------------------------------------------
// SGEMM: C[M,N] = A[M,K] @ B[K,N], all row-major, fp32.
// BM=BN=128, BK=8, TM=TN=8, 256 threads. M,N multiples of 128, K multiple of 8.
// ---------------------------------------------------------------------------
__global__ __launch_bounds__(256, 2)
void sgemm128_kernel(int M, int N, int K,
                     const float* __restrict__ A,
                     const float* __restrict__ B,
                     float* __restrict__ C)
{
    const int BM = 128, BN = 128, BK = 8, TM = 8, TN = 8;
    __shared__ float As[BK][BM];
    __shared__ float Bs[BK][BN];

    const int tid  = threadIdx.x;
    const int cRow = blockIdx.y;
    const int cCol = blockIdx.x;

    A += (size_t)cRow * BM * K;
    B += (size_t)cCol * BN;
    C += (size_t)cRow * BM * N + (size_t)cCol * BN;

    const int innerRowA = tid >> 1;          // 0..127
    const int innerColA = (tid & 1) * 4;     // 0 or 4
    const int innerRowB = tid >> 5;          // 0..7
    const int innerColB = (tid & 31) * 4;    // 0..124

    const int threadRow = tid >> 4;          // 0..15
    const int threadCol = tid & 15;          // 0..15

    float acc[TM][TN];
    #pragma unroll
    for (int i = 0; i < TM; i++)
        #pragma unroll
        for (int j = 0; j < TN; j++) acc[i][j] = 0.0f;

    float regM[TM], regN[TN];

    for (int bk = 0; bk < K; bk += BK) {
        float4 a = *reinterpret_cast<const float4*>(A + (size_t)innerRowA * K + innerColA);
        As[innerColA + 0][innerRowA] = a.x;
        As[innerColA + 1][innerRowA] = a.y;
        As[innerColA + 2][innerRowA] = a.z;
        As[innerColA + 3][innerRowA] = a.w;
        *reinterpret_cast<float4*>(&Bs[innerRowB][innerColB]) =
            *reinterpret_cast<const float4*>(B + (size_t)innerRowB * N + innerColB);
        __syncthreads();

        A += BK;
        B += (size_t)BK * N;

        #pragma unroll
        for (int k = 0; k < BK; k++) {
            #pragma unroll
            for (int i = 0; i < TM; i++) regM[i] = As[k][threadRow * TM + i];
            #pragma unroll
            for (int j = 0; j < TN; j++) regN[j] = Bs[k][threadCol * TN + j];
            #pragma unroll
            for (int i = 0; i < TM; i++)
                #pragma unroll
                for (int j = 0; j < TN; j++)
                    acc[i][j] += regM[i] * regN[j];
        }
        __syncthreads();
    }

    #pragma unroll
    for (int i = 0; i < TM; i++) {
        float* crow = C + (size_t)(threadRow * TM + i) * N + threadCol * TN;
        #pragma unroll
        for (int j = 0; j < TN; j += 4) {
            float4 t = make_float4(acc[i][j], acc[i][j+1], acc[i][j+2], acc[i][j+3]);
            *reinterpret_cast<float4*>(crow + j) = t;
        }
    }
}

// ---------------------------------------------------------------------------
// Local attention: one block per row m = (b*HW + hw)*S + s, one warp per head.
// qkv layout per row: [0,512) q | [512,1024) k | [1024,1536) v ; head h at h*64.
// Zero-padded windows participate in the softmax with logit = bias (dot = 0),
// matching the reference's zero-pad-then-softmax semantics.
// ---------------------------------------------------------------------------
__global__ __launch_bounds__(256)
void local_attn_kernel(const float* __restrict__ qkv,
                       const float* __restrict__ pos_bias,
                       float* __restrict__ out)
{
    const int m    = blockIdx.x;        // 0..32767
    const int seq  = m & (S_LEN - 1);
    const int base = m - seq;           // row index of s=0 in this sequence
    const int h    = threadIdx.x >> 5;
    const int lane = threadIdx.x & 31;

    const float* qp = qkv + (size_t)m * N_QKV + h * DK;
    const float q0 = qp[lane]      * 0.125f;   // 1/sqrt(64)
    const float q1 = qp[lane + 32] * 0.125f;

    const float* bias_row = pos_bias + ((size_t)h * S_LEN + seq) * KSIZE;

    float logit[KSIZE];
    #pragma unroll
    for (int j = 0; j < KSIZE; j++) {
        const int s2 = seq + j - PAD;
        float p = 0.0f;
        if (s2 >= 0 && s2 < S_LEN) {
            const float* kp = qkv + (size_t)(base + s2) * N_QKV + D_MODEL + h * DK;
            p = q0 * kp[lane] + q1 * kp[lane + 32];
        }
        #pragma unroll
        for (int off = 16; off > 0; off >>= 1)
            p += __shfl_xor_sync(0xffffffffu, p, off);
        logit[j] = p + bias_row[j];
    }

    float mx = logit[0];
    #pragma unroll
    for (int j = 1; j < KSIZE; j++) mx = fmaxf(mx, logit[j]);
    float e[KSIZE], sum = 0.0f;
    #pragma unroll
    for (int j = 0; j < KSIZE; j++) { e[j] = __expf(logit[j] - mx); sum += e[j]; }
    const float inv = 1.0f / sum;

    float o0 = 0.0f, o1 = 0.0f;
    #pragma unroll
    for (int j = 0; j < KSIZE; j++) {
        const int s2 = seq + j - PAD;
        if (s2 >= 0 && s2 < S_LEN) {
            const float* vp = qkv + (size_t)(base + s2) * N_QKV + 2 * D_MODEL + h * DK;
            const float a = e[j] * inv;
            o0 += a * vp[lane];
            o1 += a * vp[lane + 32];
        }
    }

    float* op = out + (size_t)m * D_MODEL + h * DK;
    op[lane]      = o0;
    op[lane + 32] = o1;
}

// ---------------------------------------------------------------------------
// Launch
// ---------------------------------------------------------------------------
extern "C" void kernel_launch(void* const* d_in, const int* in_sizes, int n_in,
                              void* d_out, int out_size)
{
    const float* inputs   = (const float*)d_in[0];  // [2,64,256,512]
    const float* pos_bias = (const float*)d_in[1];  // [8,256,7]
    const float* W_qkv    = (const float*)d_in[2];  // [512,1536]
    const float* W_out    = (const float*)d_in[3];  // [512,512]
    float*       out      = (float*)d_out;          // [2,64,256,512]

    float* qkv = nullptr;
    float* att = nullptr;
    cudaGetSymbolAddress((void**)&qkv, g_qkv);
    cudaGetSymbolAddress((void**)&att, g_att);

    // 1) QKV projection: [32768,512] @ [512,1536]
    {
        dim3 grid(N_QKV / 128, M_ROWS / 128);
        sgemm128_kernel<<<grid, 256>>>(M_ROWS, N_QKV, K_DIM, inputs, W_qkv, qkv);
    }
    // 2) Local windowed attention
    local_attn_kernel<<<M_ROWS, 256>>>(qkv, pos_bias, att);
    // 3) Output projection: [32768,512] @ [512,512]
    {
        dim3 grid(D_MODEL / 128, M_ROWS / 128);
        sgemm128_kernel<<<grid, 256>>>(M_ROWS, D_MODEL, K_DIM, att, W_out, out);
    }
}

// round 4
// speedup vs baseline: 2.2092x; 2.2092x over previous
#include <cuda_runtime.h>
#include <cuda_bf16.h>
#include <cstdint>

// ---------------- problem constants ----------------
#define HEADS   8
#define DK      64
#define KSIZE   7
#define PAD     3
#define S_LEN   256
#define D_MODEL 512
#define M_ROWS  32768            // B*HW*S
#define N_QKV   1536
#define K_DIM   512

// ---------------- GEMM tiling ----------------
#define BM 128
#define BN 128
#define BK 32
#define NCHUNK (K_DIM / BK)      // 16
#define PADK 40                  // padded bf16 row stride (80 B -> conflict-free frags)
#define TILE_BYTES (BM * PADK * 2)       // 10240
#define BUF_BYTES  (4 * TILE_BYTES)      // Ahi|Alo|Bhi|Blo = 40960
#define SMEM_TOTAL (2 * BUF_BYTES)       // 81920 (double buffered)

// ---------------- scratch (__device__ globals; no allocs allowed) ----------
__device__ float          g_qkv  [(size_t)M_ROWS * N_QKV];     // 192 MiB
__device__ __nv_bfloat16  g_ahi  [(size_t)M_ROWS * K_DIM];
__device__ __nv_bfloat16  g_alo  [(size_t)M_ROWS * K_DIM];
__device__ __nv_bfloat16  g_atthi[(size_t)M_ROWS * D_MODEL];
__device__ __nv_bfloat16  g_attlo[(size_t)M_ROWS * D_MODEL];
__device__ __nv_bfloat16  g_wqhi [(size_t)N_QKV * K_DIM];
__device__ __nv_bfloat16  g_wqlo [(size_t)N_QKV * K_DIM];
__device__ __nv_bfloat16  g_wohi [(size_t)D_MODEL * K_DIM];
__device__ __nv_bfloat16  g_wolo [(size_t)D_MODEL * K_DIM];

// ---------------- helpers ----------------
__device__ __forceinline__ uint32_t smem_u32(const void* p) {
    uint32_t a;
    asm("{ .reg .u64 t; cvta.to.shared.u64 t, %1; cvt.u32.u64 %0, t; }" : "=r"(a) : "l"(p));
    return a;
}
__device__ __forceinline__ uint32_t lds32(uint32_t addr) {
    uint32_t v;
    asm volatile("ld.shared.b32 %0, [%1];" : "=r"(v) : "r"(addr));
    return v;
}
#define CP_ASYNC16(sa, gp) \
    asm volatile("cp.async.cg.shared.global [%0], [%1], 16;" :: "r"(sa), "l"(gp) : "memory")
#define CP_COMMIT() asm volatile("cp.async.commit_group;" ::: "memory")
#define CP_WAIT1()  asm volatile("cp.async.wait_group 1;" ::: "memory")
#define CP_WAIT0()  asm volatile("cp.async.wait_group 0;" ::: "memory")

__device__ __forceinline__ void mma_bf16(float* d, const uint32_t* a, const uint32_t* b) {
    asm volatile(
        "mma.sync.aligned.m16n8k16.row.col.f32.bf16.bf16.f32 "
        "{%0,%1,%2,%3}, {%4,%5,%6,%7}, {%8,%9}, {%0,%1,%2,%3};"
        : "+f"(d[0]), "+f"(d[1]), "+f"(d[2]), "+f"(d[3])
        : "r"(a[0]), "r"(a[1]), "r"(a[2]), "r"(a[3]), "r"(b[0]), "r"(b[1]));
}

// ---------------------------------------------------------------------------
// Conversion kernels: fp32 -> (hi, lo) bf16 split
// ---------------------------------------------------------------------------
__global__ __launch_bounds__(256)
void convert_act_kernel(const float* __restrict__ in,
                        __nv_bfloat16* __restrict__ hi,
                        __nv_bfloat16* __restrict__ lo)
{
    size_t i = ((size_t)blockIdx.x * 256 + threadIdx.x) * 4;
    float4 v = *reinterpret_cast<const float4*>(in + i);
    __nv_bfloat16 h0 = __float2bfloat16(v.x), h1 = __float2bfloat16(v.y);
    __nv_bfloat16 h2 = __float2bfloat16(v.z), h3 = __float2bfloat16(v.w);
    __nv_bfloat16 l0 = __float2bfloat16(v.x - __bfloat162float(h0));
    __nv_bfloat16 l1 = __float2bfloat16(v.y - __bfloat162float(h1));
    __nv_bfloat16 l2 = __float2bfloat16(v.z - __bfloat162float(h2));
    __nv_bfloat16 l3 = __float2bfloat16(v.w - __bfloat162float(h3));
    *reinterpret_cast<__nv_bfloat162*>(hi + i)     = __nv_bfloat162(h0, h1);
    *reinterpret_cast<__nv_bfloat162*>(hi + i + 2) = __nv_bfloat162(h2, h3);
    *reinterpret_cast<__nv_bfloat162*>(lo + i)     = __nv_bfloat162(l0, l1);
    *reinterpret_cast<__nv_bfloat162*>(lo + i + 2) = __nv_bfloat162(l2, l3);
}

// W [Kd, Nd] row-major fp32 -> Wt [Nd, Kd] bf16 hi/lo (K-contiguous, transposed)
__global__ __launch_bounds__(256)
void convert_w_kernel(const float* __restrict__ W,
                      __nv_bfloat16* __restrict__ hi,
                      __nv_bfloat16* __restrict__ lo, int Kd, int Nd)
{
    size_t idx = (size_t)blockIdx.x * 256 + threadIdx.x;
    int n = (int)(idx / Kd);
    int k = (int)(idx % Kd);
    float x = W[(size_t)k * Nd + n];
    __nv_bfloat16 h = __float2bfloat16(x);
    hi[idx] = h;
    lo[idx] = __float2bfloat16(x - __bfloat162float(h));
}

// ---------------------------------------------------------------------------
// bf16 split GEMM via mma.sync:  C[M, Ntot] = A[M,512] @ B^T  (B is [Ntot,512])
// CTA 128x128, BK=32, 8 warps (warp tile 64x32), cp.async double buffer.
// 3 passes: Ahi*Bhi + Ahi*Blo + Alo*Bhi.
// ---------------------------------------------------------------------------
__global__ __launch_bounds__(256)
void gemm_mma_kernel(const __nv_bfloat16* __restrict__ Ahi,
                     const __nv_bfloat16* __restrict__ Alo,
                     const __nv_bfloat16* __restrict__ Bhi,
                     const __nv_bfloat16* __restrict__ Blo,
                     float* __restrict__ C, int Ntot)
{
    extern __shared__ char smem[];
    const uint32_t sb = smem_u32(smem);
    const int tid = threadIdx.x;
    const int wid = tid >> 5;
    const int lid = tid & 31;
    const int warp_m = wid & 1;          // 0..1 -> 64 rows each
    const int warp_n = wid >> 1;         // 0..3 -> 32 cols each
    const int g   = lid >> 2;            // group id 0..7
    const int cp2 = (lid & 3) * 2;       // col pair

    const int m0 = blockIdx.y * BM;
    const int n0 = blockIdx.x * BN;

    const __nv_bfloat16* baseptr[4] = {
        Ahi + (size_t)m0 * K_DIM, Alo + (size_t)m0 * K_DIM,
        Bhi + (size_t)n0 * K_DIM, Blo + (size_t)n0 * K_DIM };

    // ---- async tile loader: chunk c -> buffer buf ----
    auto load_chunk = [&](int c, int buf) {
        const int kof = c * BK;
        const uint32_t sbase = sb + buf * BUF_BYTES;
        #pragma unroll
        for (int i = 0; i < 8; i++) {
            const int u    = tid + i * 256;          // 0..2047
            const int t    = u >> 9;                 // tile 0..3
            const int v    = u & 511;
            const int row  = v >> 2;
            const int quad = v & 3;
            const uint32_t sa = sbase + t * TILE_BYTES + row * (PADK * 2) + quad * 16;
            const __nv_bfloat16* gp = baseptr[t] + (size_t)row * K_DIM + kof + quad * 8;
            CP_ASYNC16(sa, gp);
        }
    };

    float acc[4][4][4];
    #pragma unroll
    for (int i = 0; i < 4; i++)
        #pragma unroll
        for (int j = 0; j < 4; j++)
            #pragma unroll
            for (int q = 0; q < 4; q++) acc[i][j][q] = 0.0f;

    load_chunk(0, 0);
    CP_COMMIT();

    for (int c = 0; c < NCHUNK; c++) {
        if (c + 1 < NCHUNK) {
            load_chunk(c + 1, (c + 1) & 1);
            CP_COMMIT();
            CP_WAIT1();
        } else {
            CP_WAIT0();
        }
        __syncthreads();

        const uint32_t sbase = sb + (c & 1) * BUF_BYTES;
        const uint32_t sAh = sbase;
        const uint32_t sAl = sbase + TILE_BYTES;
        const uint32_t sBh = sbase + 2 * TILE_BYTES;
        const uint32_t sBl = sbase + 3 * TILE_BYTES;

        #pragma unroll
        for (int ks = 0; ks < 2; ks++) {
            const int kcol = ks * 16 + cp2;          // bf16 col within chunk
            // A-fragment byte offsets (4 per m-tile)
            uint32_t aoff[4];
            #pragma unroll
            for (int mt = 0; mt < 4; mt++)
                aoff[mt] = (uint32_t)((warp_m * 64 + mt * 16 + g) * (PADK * 2) + kcol * 2);
            uint32_t boff[4];
            #pragma unroll
            for (int nt = 0; nt < 4; nt++)
                boff[nt] = (uint32_t)((warp_n * 32 + nt * 8 + g) * (PADK * 2) + kcol * 2);

            uint32_t rAh[4][4], rBh[4][2], rT[4][4];

            #pragma unroll
            for (int mt = 0; mt < 4; mt++) {
                rAh[mt][0] = lds32(sAh + aoff[mt]);
                rAh[mt][1] = lds32(sAh + aoff[mt] + 8 * (PADK * 2));
                rAh[mt][2] = lds32(sAh + aoff[mt] + 16);
                rAh[mt][3] = lds32(sAh + aoff[mt] + 8 * (PADK * 2) + 16);
            }
            #pragma unroll
            for (int nt = 0; nt < 4; nt++) {
                rBh[nt][0] = lds32(sBh + boff[nt]);
                rBh[nt][1] = lds32(sBh + boff[nt] + 16);
            }
            // pass 1: Ahi * Bhi
            #pragma unroll
            for (int mt = 0; mt < 4; mt++)
                #pragma unroll
                for (int nt = 0; nt < 4; nt++)
                    mma_bf16(acc[mt][nt], rAh[mt], rBh[nt]);

            // pass 2: Ahi * Blo
            #pragma unroll
            for (int nt = 0; nt < 4; nt++) {
                rT[nt][0] = lds32(sBl + boff[nt]);
                rT[nt][1] = lds32(sBl + boff[nt] + 16);
            }
            #pragma unroll
            for (int mt = 0; mt < 4; mt++)
                #pragma unroll
                for (int nt = 0; nt < 4; nt++)
                    mma_bf16(acc[mt][nt], rAh[mt], rT[nt]);

            // pass 3: Alo * Bhi
            #pragma unroll
            for (int mt = 0; mt < 4; mt++) {
                rT[mt][0] = lds32(sAl + aoff[mt]);
                rT[mt][1] = lds32(sAl + aoff[mt] + 8 * (PADK * 2));
                rT[mt][2] = lds32(sAl + aoff[mt] + 16);
                rT[mt][3] = lds32(sAl + aoff[mt] + 8 * (PADK * 2) + 16);
            }
            #pragma unroll
            for (int mt = 0; mt < 4; mt++)
                #pragma unroll
                for (int nt = 0; nt < 4; nt++)
                    mma_bf16(acc[mt][nt], rT[mt], rBh[nt]);
        }
        __syncthreads();
    }

    // ---- epilogue: fp32 stores ----
    #pragma unroll
    for (int mt = 0; mt < 4; mt++) {
        const int row = m0 + warp_m * 64 + mt * 16 + g;
        #pragma unroll
        for (int nt = 0; nt < 4; nt++) {
            const int col = n0 + warp_n * 32 + nt * 8 + cp2;
            *reinterpret_cast<float2*>(C + (size_t)row * Ntot + col) =
                make_float2(acc[mt][nt][0], acc[mt][nt][1]);
            *reinterpret_cast<float2*>(C + (size_t)(row + 8) * Ntot + col) =
                make_float2(acc[mt][nt][2], acc[mt][nt][3]);
        }
    }
}

// ---------------------------------------------------------------------------
// Local attention: one block per row, one warp per head. fp32 math; writes
// bf16 hi/lo split output (fused conversion for GEMM2).
// ---------------------------------------------------------------------------
__global__ __launch_bounds__(256)
void local_attn_kernel(const float* __restrict__ qkv,
                       const float* __restrict__ pos_bias,
                       __nv_bfloat16* __restrict__ ohi,
                       __nv_bfloat16* __restrict__ olo)
{
    const int m    = blockIdx.x;
    const int seq  = m & (S_LEN - 1);
    const int base = m - seq;
    const int h    = threadIdx.x >> 5;
    const int lane = threadIdx.x & 31;

    const float* qp = qkv + (size_t)m * N_QKV + h * DK;
    const float q0 = qp[lane]      * 0.125f;
    const float q1 = qp[lane + 32] * 0.125f;

    const float* bias_row = pos_bias + ((size_t)h * S_LEN + seq) * KSIZE;

    float logit[KSIZE];
    #pragma unroll
    for (int j = 0; j < KSIZE; j++) {
        const int s2 = seq + j - PAD;
        float p = 0.0f;
        if (s2 >= 0 && s2 < S_LEN) {
            const float* kp = qkv + (size_t)(base + s2) * N_QKV + D_MODEL + h * DK;
            p = q0 * kp[lane] + q1 * kp[lane + 32];
        }
        #pragma unroll
        for (int off = 16; off > 0; off >>= 1)
            p += __shfl_xor_sync(0xffffffffu, p, off);
        logit[j] = p + bias_row[j];
    }

    float mx = logit[0];
    #pragma unroll
    for (int j = 1; j < KSIZE; j++) mx = fmaxf(mx, logit[j]);
    float e[KSIZE], sum = 0.0f;
    #pragma unroll
    for (int j = 0; j < KSIZE; j++) { e[j] = __expf(logit[j] - mx); sum += e[j]; }
    const float inv = 1.0f / sum;

    float o0 = 0.0f, o1 = 0.0f;
    #pragma unroll
    for (int j = 0; j < KSIZE; j++) {
        const int s2 = seq + j - PAD;
        if (s2 >= 0 && s2 < S_LEN) {
            const float* vp = qkv + (size_t)(base + s2) * N_QKV + 2 * D_MODEL + h * DK;
            const float a = e[j] * inv;
            o0 += a * vp[lane];
            o1 += a * vp[lane + 32];
        }
    }

    const size_t ob = (size_t)m * D_MODEL + h * DK;
    __nv_bfloat16 h0 = __float2bfloat16(o0);
    __nv_bfloat16 h1 = __float2bfloat16(o1);
    ohi[ob + lane]      = h0;
    ohi[ob + lane + 32] = h1;
    olo[ob + lane]      = __float2bfloat16(o0 - __bfloat162float(h0));
    olo[ob + lane + 32] = __float2bfloat16(o1 - __bfloat162float(h1));
}

// ---------------------------------------------------------------------------
// Launch
// ---------------------------------------------------------------------------
extern "C" void kernel_launch(void* const* d_in, const int* in_sizes, int n_in,
                              void* d_out, int out_size)
{
    const float* inputs   = (const float*)d_in[0];
    const float* pos_bias = (const float*)d_in[1];
    const float* W_qkv    = (const float*)d_in[2];
    const float* W_out    = (const float*)d_in[3];
    float*       out      = (float*)d_out;

    float *qkv; __nv_bfloat16 *ahi, *alo, *atthi, *attlo, *wqhi, *wqlo, *wohi, *wolo;
    cudaGetSymbolAddress((void**)&qkv,   g_qkv);
    cudaGetSymbolAddress((void**)&ahi,   g_ahi);
    cudaGetSymbolAddress((void**)&alo,   g_alo);
    cudaGetSymbolAddress((void**)&atthi, g_atthi);
    cudaGetSymbolAddress((void**)&attlo, g_attlo);
    cudaGetSymbolAddress((void**)&wqhi,  g_wqhi);
    cudaGetSymbolAddress((void**)&wqlo,  g_wqlo);
    cudaGetSymbolAddress((void**)&wohi,  g_wohi);
    cudaGetSymbolAddress((void**)&wolo,  g_wolo);

    cudaFuncSetAttribute(gemm_mma_kernel,
                         cudaFuncAttributeMaxDynamicSharedMemorySize, SMEM_TOTAL);

    // 0) Conversions
    convert_act_kernel<<<(M_ROWS * K_DIM / 4) / 256, 256>>>(inputs, ahi, alo);
    convert_w_kernel<<<(N_QKV * K_DIM) / 256, 256>>>(W_qkv, wqhi, wqlo, K_DIM, N_QKV);
    convert_w_kernel<<<(D_MODEL * K_DIM) / 256, 256>>>(W_out, wohi, wolo, K_DIM, D_MODEL);

    // 1) QKV projection: [32768,512] @ [512,1536]
    {
        dim3 grid(N_QKV / BN, M_ROWS / BM);     // x = N (fastest) for L2 reuse of A
        gemm_mma_kernel<<<grid, 256, SMEM_TOTAL>>>(ahi, alo, wqhi, wqlo, qkv, N_QKV);
    }
    // 2) Local windowed attention
    local_attn_kernel<<<M_ROWS, 256>>>(qkv, pos_bias, atthi, attlo);
    // 3) Output projection: [32768,512] @ [512,512]
    {
        dim3 grid(D_MODEL / BN, M_ROWS / BM);
        gemm_mma_kernel<<<grid, 256, SMEM_TOTAL>>>(atthi, attlo, wohi, wolo, out, D_MODEL);
    }
}

// round 5
// speedup vs baseline: 3.2816x; 1.4854x over previous
#include <cuda_runtime.h>
#include <cuda_fp16.h>
#include <cstdint>

// ---------------- problem constants ----------------
#define HEADS   8
#define DK      64
#define KSIZE   7
#define PAD     3
#define S_LEN   256
#define D_MODEL 512
#define M_ROWS  32768            // B*HW*S
#define N_QKV   1536
#define K_DIM   512

// ---------------- GEMM tiling ----------------
#define BM 128
#define BN 128
#define BK 32
#define NCHUNK (K_DIM / BK)      // 16
#define PADK 40                  // padded fp16 row stride (80 B)
#define TILE_BYTES (BM * PADK * 2)       // 10240
#define BUF_BYTES  (3 * TILE_BYTES)      // A | Bhi | Blo = 30720
#define SMEM_TOTAL (2 * BUF_BYTES)       // 61440 (double buffered)

// ---------------- scratch (__device__ globals; no allocs allowed) ----------
__device__ float   g_qkv [(size_t)M_ROWS * N_QKV];      // 192 MiB
__device__ __half  g_a   [(size_t)M_ROWS * K_DIM];      // fp16 activations
__device__ __half  g_att [(size_t)M_ROWS * D_MODEL];    // fp16 attention out
__device__ __half  g_wqhi[(size_t)N_QKV * K_DIM];
__device__ __half  g_wqlo[(size_t)N_QKV * K_DIM];
__device__ __half  g_wohi[(size_t)D_MODEL * K_DIM];
__device__ __half  g_wolo[(size_t)D_MODEL * K_DIM];

// ---------------- helpers ----------------
__device__ __forceinline__ uint32_t smem_u32(const void* p) {
    uint32_t a;
    asm("{ .reg .u64 t; cvta.to.shared.u64 t, %1; cvt.u32.u64 %0, t; }" : "=r"(a) : "l"(p));
    return a;
}
__device__ __forceinline__ uint32_t lds32(uint32_t addr) {
    uint32_t v;
    asm volatile("ld.shared.b32 %0, [%1];" : "=r"(v) : "r"(addr));
    return v;
}
#define CP_ASYNC16(sa, gp) \
    asm volatile("cp.async.cg.shared.global [%0], [%1], 16;" :: "r"(sa), "l"(gp) : "memory")
#define CP_COMMIT() asm volatile("cp.async.commit_group;" ::: "memory")
#define CP_WAIT1()  asm volatile("cp.async.wait_group 1;" ::: "memory")
#define CP_WAIT0()  asm volatile("cp.async.wait_group 0;" ::: "memory")

__device__ __forceinline__ void mma_f16(float* d, const uint32_t* a, const uint32_t* b) {
    asm volatile(
        "mma.sync.aligned.m16n8k16.row.col.f32.f16.f16.f32 "
        "{%0,%1,%2,%3}, {%4,%5,%6,%7}, {%8,%9}, {%0,%1,%2,%3};"
        : "+f"(d[0]), "+f"(d[1]), "+f"(d[2]), "+f"(d[3])
        : "r"(a[0]), "r"(a[1]), "r"(a[2]), "r"(a[3]), "r"(b[0]), "r"(b[1]));
}

// ---------------------------------------------------------------------------
// Conversions
// ---------------------------------------------------------------------------
__global__ __launch_bounds__(256)
void convert_act_kernel(const float* __restrict__ in, __half* __restrict__ out)
{
    size_t i = ((size_t)blockIdx.x * 256 + threadIdx.x) * 4;
    float4 v = *reinterpret_cast<const float4*>(in + i);
    __half2 p0 = __floats2half2_rn(v.x, v.y);
    __half2 p1 = __floats2half2_rn(v.z, v.w);
    *reinterpret_cast<__half2*>(out + i)     = p0;
    *reinterpret_cast<__half2*>(out + i + 2) = p1;
}

// W [Kd, Nd] row-major fp32 -> Wt [Nd, Kd] fp16 hi/lo split (K-contiguous)
__global__ __launch_bounds__(256)
void convert_w_kernel(const float* __restrict__ W,
                      __half* __restrict__ hi,
                      __half* __restrict__ lo, int Kd, int Nd)
{
    size_t idx = (size_t)blockIdx.x * 256 + threadIdx.x;
    int n = (int)(idx / Kd);
    int k = (int)(idx % Kd);
    float x = W[(size_t)k * Nd + n];
    __half h = __float2half_rn(x);
    hi[idx] = h;
    lo[idx] = __float2half_rn(x - __half2float(h));
}

// ---------------------------------------------------------------------------
// fp16 2-pass split GEMM:  C[M, Ntot] = A[M,512] @ (Bhi + Blo)^T
// CTA 128x128, BK=32, 8 warps (warp tile 64x32), cp.async double buffer,
// 2 CTAs/SM. Passes: A*Bhi + A*Blo (A fp16, B split fp16 -> err ~2^-11 from A).
// ---------------------------------------------------------------------------
__global__ __launch_bounds__(256, 2)
void gemm_mma_kernel(const __half* __restrict__ A,
                     const __half* __restrict__ Bhi,
                     const __half* __restrict__ Blo,
                     float* __restrict__ C, int Ntot)
{
    extern __shared__ char smem[];
    const uint32_t sb = smem_u32(smem);
    const int tid = threadIdx.x;
    const int wid = tid >> 5;
    const int lid = tid & 31;
    const int warp_m = wid & 1;          // 0..1 -> 64 rows each
    const int warp_n = wid >> 1;         // 0..3 -> 32 cols each
    const int g   = lid >> 2;            // 0..7
    const int cp2 = (lid & 3) * 2;

    const int m0 = blockIdx.y * BM;
    const int n0 = blockIdx.x * BN;

    const __half* baseptr[3] = {
        A   + (size_t)m0 * K_DIM,
        Bhi + (size_t)n0 * K_DIM,
        Blo + (size_t)n0 * K_DIM };

    // ---- async tile loader: chunk c -> buffer buf (3 tiles x 128 rows x 4x16B)
    auto load_chunk = [&](int c, int buf) {
        const int kof = c * BK;
        const uint32_t sbase = sb + buf * BUF_BYTES;
        #pragma unroll
        for (int i = 0; i < 6; i++) {
            const int u    = tid + i * 256;          // 0..1535
            const int t    = u >> 9;                 // tile 0..2
            const int v    = u & 511;
            const int row  = v >> 2;
            const int quad = v & 3;
            const uint32_t sa = sbase + t * TILE_BYTES + row * (PADK * 2) + quad * 16;
            const __half* gp = baseptr[t] + (size_t)row * K_DIM + kof + quad * 8;
            CP_ASYNC16(sa, gp);
        }
    };

    float acc[4][4][4];
    #pragma unroll
    for (int i = 0; i < 4; i++)
        #pragma unroll
        for (int j = 0; j < 4; j++)
            #pragma unroll
            for (int q = 0; q < 4; q++) acc[i][j][q] = 0.0f;

    load_chunk(0, 0);
    CP_COMMIT();

    for (int c = 0; c < NCHUNK; c++) {
        if (c + 1 < NCHUNK) {
            load_chunk(c + 1, (c + 1) & 1);
            CP_COMMIT();
            CP_WAIT1();
        } else {
            CP_WAIT0();
        }
        __syncthreads();

        const uint32_t sbase = sb + (c & 1) * BUF_BYTES;
        const uint32_t sA  = sbase;
        const uint32_t sBh = sbase + TILE_BYTES;
        const uint32_t sBl = sbase + 2 * TILE_BYTES;

        #pragma unroll
        for (int ks = 0; ks < 2; ks++) {
            const int kcol = ks * 16 + cp2;
            uint32_t aoff[4], boff[4];
            #pragma unroll
            for (int mt = 0; mt < 4; mt++)
                aoff[mt] = (uint32_t)((warp_m * 64 + mt * 16 + g) * (PADK * 2) + kcol * 2);
            #pragma unroll
            for (int nt = 0; nt < 4; nt++)
                boff[nt] = (uint32_t)((warp_n * 32 + nt * 8 + g) * (PADK * 2) + kcol * 2);

            uint32_t rA[4][4], rB[4][2];

            #pragma unroll
            for (int mt = 0; mt < 4; mt++) {
                rA[mt][0] = lds32(sA + aoff[mt]);
                rA[mt][1] = lds32(sA + aoff[mt] + 8 * (PADK * 2));
                rA[mt][2] = lds32(sA + aoff[mt] + 16);
                rA[mt][3] = lds32(sA + aoff[mt] + 8 * (PADK * 2) + 16);
            }
            // pass 1: A * Bhi
            #pragma unroll
            for (int nt = 0; nt < 4; nt++) {
                rB[nt][0] = lds32(sBh + boff[nt]);
                rB[nt][1] = lds32(sBh + boff[nt] + 16);
            }
            #pragma unroll
            for (int mt = 0; mt < 4; mt++)
                #pragma unroll
                for (int nt = 0; nt < 4; nt++)
                    mma_f16(acc[mt][nt], rA[mt], rB[nt]);

            // pass 2: A * Blo (A frags reused)
            #pragma unroll
            for (int nt = 0; nt < 4; nt++) {
                rB[nt][0] = lds32(sBl + boff[nt]);
                rB[nt][1] = lds32(sBl + boff[nt] + 16);
            }
            #pragma unroll
            for (int mt = 0; mt < 4; mt++)
                #pragma unroll
                for (int nt = 0; nt < 4; nt++)
                    mma_f16(acc[mt][nt], rA[mt], rB[nt]);
        }
        __syncthreads();
    }

    // ---- epilogue: fp32 stores ----
    #pragma unroll
    for (int mt = 0; mt < 4; mt++) {
        const int row = m0 + warp_m * 64 + mt * 16 + g;
        #pragma unroll
        for (int nt = 0; nt < 4; nt++) {
            const int col = n0 + warp_n * 32 + nt * 8 + cp2;
            *reinterpret_cast<float2*>(C + (size_t)row * Ntot + col) =
                make_float2(acc[mt][nt][0], acc[mt][nt][1]);
            *reinterpret_cast<float2*>(C + (size_t)(row + 8) * Ntot + col) =
                make_float2(acc[mt][nt][2], acc[mt][nt][3]);
        }
    }
}

// ---------------------------------------------------------------------------
// Local attention: one block per row, one warp per head. fp32 math, fp16 out.
// ---------------------------------------------------------------------------
__global__ __launch_bounds__(256)
void local_attn_kernel(const float* __restrict__ qkv,
                       const float* __restrict__ pos_bias,
                       __half* __restrict__ out)
{
    const int m    = blockIdx.x;
    const int seq  = m & (S_LEN - 1);
    const int base = m - seq;
    const int h    = threadIdx.x >> 5;
    const int lane = threadIdx.x & 31;

    const float* qp = qkv + (size_t)m * N_QKV + h * DK;
    const float q0 = qp[lane]      * 0.125f;
    const float q1 = qp[lane + 32] * 0.125f;

    const float* bias_row = pos_bias + ((size_t)h * S_LEN + seq) * KSIZE;

    float logit[KSIZE];
    #pragma unroll
    for (int j = 0; j < KSIZE; j++) {
        const int s2 = seq + j - PAD;
        float p = 0.0f;
        if (s2 >= 0 && s2 < S_LEN) {
            const float* kp = qkv + (size_t)(base + s2) * N_QKV + D_MODEL + h * DK;
            p = q0 * kp[lane] + q1 * kp[lane + 32];
        }
        #pragma unroll
        for (int off = 16; off > 0; off >>= 1)
            p += __shfl_xor_sync(0xffffffffu, p, off);
        logit[j] = p + bias_row[j];
    }

    float mx = logit[0];
    #pragma unroll
    for (int j = 1; j < KSIZE; j++) mx = fmaxf(mx, logit[j]);
    float e[KSIZE], sum = 0.0f;
    #pragma unroll
    for (int j = 0; j < KSIZE; j++) { e[j] = __expf(logit[j] - mx); sum += e[j]; }
    const float inv = 1.0f / sum;

    float o0 = 0.0f, o1 = 0.0f;
    #pragma unroll
    for (int j = 0; j < KSIZE; j++) {
        const int s2 = seq + j - PAD;
        if (s2 >= 0 && s2 < S_LEN) {
            const float* vp = qkv + (size_t)(base + s2) * N_QKV + 2 * D_MODEL + h * DK;
            const float a = e[j] * inv;
            o0 += a * vp[lane];
            o1 += a * vp[lane + 32];
        }
    }

    const size_t ob = (size_t)m * D_MODEL + h * DK;
    out[ob + lane]      = __float2half_rn(o0);
    out[ob + lane + 32] = __float2half_rn(o1);
}

// ---------------------------------------------------------------------------
// Launch
// ---------------------------------------------------------------------------
extern "C" void kernel_launch(void* const* d_in, const int* in_sizes, int n_in,
                              void* d_out, int out_size)
{
    const float* inputs   = (const float*)d_in[0];
    const float* pos_bias = (const float*)d_in[1];
    const float* W_qkv    = (const float*)d_in[2];
    const float* W_out    = (const float*)d_in[3];
    float*       out      = (float*)d_out;

    float *qkv; __half *a16, *att, *wqhi, *wqlo, *wohi, *wolo;
    cudaGetSymbolAddress((void**)&qkv,  g_qkv);
    cudaGetSymbolAddress((void**)&a16,  g_a);
    cudaGetSymbolAddress((void**)&att,  g_att);
    cudaGetSymbolAddress((void**)&wqhi, g_wqhi);
    cudaGetSymbolAddress((void**)&wqlo, g_wqlo);
    cudaGetSymbolAddress((void**)&wohi, g_wohi);
    cudaGetSymbolAddress((void**)&wolo, g_wolo);

    cudaFuncSetAttribute(gemm_mma_kernel,
                         cudaFuncAttributeMaxDynamicSharedMemorySize, SMEM_TOTAL);

    // 0) Conversions
    convert_act_kernel<<<(M_ROWS * K_DIM / 4) / 256, 256>>>(inputs, a16);
    convert_w_kernel<<<(N_QKV * K_DIM) / 256, 256>>>(W_qkv, wqhi, wqlo, K_DIM, N_QKV);
    convert_w_kernel<<<(D_MODEL * K_DIM) / 256, 256>>>(W_out, wohi, wolo, K_DIM, D_MODEL);

    // 1) QKV projection: [32768,512] @ [512,1536]
    {
        dim3 grid(N_QKV / BN, M_ROWS / BM);
        gemm_mma_kernel<<<grid, 256, SMEM_TOTAL>>>(a16, wqhi, wqlo, qkv, N_QKV);
    }
    // 2) Local windowed attention
    local_attn_kernel<<<M_ROWS, 256>>>(qkv, pos_bias, att);
    // 3) Output projection: [32768,512] @ [512,512]
    {
        dim3 grid(D_MODEL / BN, M_ROWS / BM);
        gemm_mma_kernel<<<grid, 256, SMEM_TOTAL>>>(att, wohi, wolo, out, D_MODEL);
    }
}

// round 6
// speedup vs baseline: 3.5522x; 1.0824x over previous
#include <cuda_runtime.h>
#include <cuda_fp16.h>
#include <cstdint>

// ---------------- problem constants ----------------
#define HEADS   8
#define DK      64
#define KSIZE   7
#define PAD     3
#define S_LEN   256
#define D_MODEL 512
#define M_ROWS  32768            // B*HW*S
#define N_QKV   1536
#define K_DIM   512

// ---------------- GEMM tiling ----------------
#define BM 128
#define BN 128
#define BK 32
#define NCHUNK (K_DIM / BK)      // 16
#define PADK 40                  // padded fp16 row stride (80 B, conflict-free)
#define ROWB (PADK * 2)          // 80 bytes
#define TILE_BYTES (BM * ROWB)           // 10240
#define BUF_BYTES  (3 * TILE_BYTES)      // A | Bhi | Blo = 30720
#define SMEM_TOTAL (2 * BUF_BYTES)       // 61440 (double buffered)

// ---------------- scratch (__device__ globals; no allocs allowed) ----------
__device__ float   g_qkv [(size_t)M_ROWS * N_QKV];      // 192 MiB
__device__ __half  g_a   [(size_t)M_ROWS * K_DIM];      // fp16 activations
__device__ __half  g_att [(size_t)M_ROWS * D_MODEL];    // fp16 attention out
__device__ __half  g_wqhi[(size_t)N_QKV * K_DIM];
__device__ __half  g_wqlo[(size_t)N_QKV * K_DIM];
__device__ __half  g_wohi[(size_t)D_MODEL * K_DIM];
__device__ __half  g_wolo[(size_t)D_MODEL * K_DIM];

// ---------------- helpers ----------------
__device__ __forceinline__ uint32_t smem_u32(const void* p) {
    uint32_t a;
    asm("{ .reg .u64 t; cvta.to.shared.u64 t, %1; cvt.u32.u64 %0, t; }" : "=r"(a) : "l"(p));
    return a;
}
#define CP_ASYNC16(sa, gp) \
    asm volatile("cp.async.cg.shared.global [%0], [%1], 16;" :: "r"(sa), "l"(gp) : "memory")
#define CP_COMMIT() asm volatile("cp.async.commit_group;" ::: "memory")
#define CP_WAIT1()  asm volatile("cp.async.wait_group 1;" ::: "memory")
#define CP_WAIT0()  asm volatile("cp.async.wait_group 0;" ::: "memory")

#define LDMATRIX_X4(r0, r1, r2, r3, addr) \
    asm volatile("ldmatrix.sync.aligned.m8n8.x4.shared.b16 {%0,%1,%2,%3}, [%4];" \
        : "=r"(r0), "=r"(r1), "=r"(r2), "=r"(r3) : "r"(addr))

__device__ __forceinline__ void mma_f16(float* d, const uint32_t* a, const uint32_t* b) {
    asm volatile(
        "mma.sync.aligned.m16n8k16.row.col.f32.f16.f16.f32 "
        "{%0,%1,%2,%3}, {%4,%5,%6,%7}, {%8,%9}, {%0,%1,%2,%3};"
        : "+f"(d[0]), "+f"(d[1]), "+f"(d[2]), "+f"(d[3])
        : "r"(a[0]), "r"(a[1]), "r"(a[2]), "r"(a[3]), "r"(b[0]), "r"(b[1]));
}

// ---------------------------------------------------------------------------
// Conversions
// ---------------------------------------------------------------------------
__global__ __launch_bounds__(256)
void convert_act_kernel(const float* __restrict__ in, __half* __restrict__ out)
{
    size_t i = ((size_t)blockIdx.x * 256 + threadIdx.x) * 4;
    float4 v = *reinterpret_cast<const float4*>(in + i);
    *reinterpret_cast<__half2*>(out + i)     = __floats2half2_rn(v.x, v.y);
    *reinterpret_cast<__half2*>(out + i + 2) = __floats2half2_rn(v.z, v.w);
}

// W [Kd, Nd] row-major fp32 -> Wt [Nd, Kd] fp16 hi/lo split (K-contiguous)
__global__ __launch_bounds__(256)
void convert_w_kernel(const float* __restrict__ W,
                      __half* __restrict__ hi,
                      __half* __restrict__ lo, int Kd, int Nd)
{
    size_t idx = (size_t)blockIdx.x * 256 + threadIdx.x;
    int n = (int)(idx / Kd);
    int k = (int)(idx % Kd);
    float x = W[(size_t)k * Nd + n];
    __half h = __float2half_rn(x);
    hi[idx] = h;
    lo[idx] = __float2half_rn(x - __half2float(h));
}

// ---------------------------------------------------------------------------
// fp16 2-pass split GEMM:  C[M, Ntot] = A[M,512] @ (Bhi + Blo)^T
// CTA 128x128, BK=32, 8 warps (warp tile 64x32), cp.async double buffer,
// 2 CTAs/SM, ldmatrix.x4 fragment loads.
// ---------------------------------------------------------------------------
__global__ __launch_bounds__(256, 2)
void gemm_mma_kernel(const __half* __restrict__ A,
                     const __half* __restrict__ Bhi,
                     const __half* __restrict__ Blo,
                     float* __restrict__ C, int Ntot)
{
    extern __shared__ char smem[];
    const uint32_t sb = smem_u32(smem);
    const int tid = threadIdx.x;
    const int wid = tid >> 5;
    const int lid = tid & 31;
    const int warp_m = wid & 1;          // 0..1 -> 64 rows each
    const int warp_n = wid >> 1;         // 0..3 -> 32 cols each
    const int g   = lid >> 2;            // 0..7
    const int cp2 = (lid & 3) * 2;

    const int m0 = blockIdx.y * BM;
    const int n0 = blockIdx.x * BN;

    // ldmatrix per-lane byte offsets (within a tile)
    // A (.x4 -> full 16x16 frag): lanes 0-15 rows 0-15 (k0-7), 16-31 rows +16B (k8-15)
    const uint32_t aByte = (uint32_t)((warp_m * 64 + (lid & 15)) * ROWB + (lid >> 4) * 16);
    // B (.x4 -> two 8x16 n-tiles): mi = lid>>3: {nt0 k0-7, nt0 k8-15, nt1 k0-7, nt1 k8-15}
    const int bmi = lid >> 3;
    const uint32_t bByte = (uint32_t)((warp_n * 32 + (bmi >> 1) * 8 + (lid & 7)) * ROWB
                                      + (bmi & 1) * 16);

    const __half* baseptr[3] = {
        A   + (size_t)m0 * K_DIM,
        Bhi + (size_t)n0 * K_DIM,
        Blo + (size_t)n0 * K_DIM };

    auto load_chunk = [&](int c, int buf) {
        const int kof = c * BK;
        const uint32_t sbase = sb + buf * BUF_BYTES;
        #pragma unroll
        for (int i = 0; i < 6; i++) {
            const int u    = tid + i * 256;          // 0..1535
            const int t    = u >> 9;                 // tile 0..2
            const int v    = u & 511;
            const int row  = v >> 2;
            const int quad = v & 3;
            const uint32_t sa = sbase + t * TILE_BYTES + row * ROWB + quad * 16;
            const __half* gp = baseptr[t] + (size_t)row * K_DIM + kof + quad * 8;
            CP_ASYNC16(sa, gp);
        }
    };

    float acc[4][4][4];
    #pragma unroll
    for (int i = 0; i < 4; i++)
        #pragma unroll
        for (int j = 0; j < 4; j++)
            #pragma unroll
            for (int q = 0; q < 4; q++) acc[i][j][q] = 0.0f;

    load_chunk(0, 0);
    CP_COMMIT();

    for (int c = 0; c < NCHUNK; c++) {
        if (c + 1 < NCHUNK) {
            load_chunk(c + 1, (c + 1) & 1);
            CP_COMMIT();
            CP_WAIT1();
        } else {
            CP_WAIT0();
        }
        __syncthreads();

        const uint32_t sbase = sb + (c & 1) * BUF_BYTES;
        const uint32_t sA  = sbase;
        const uint32_t sBh = sbase + TILE_BYTES;
        const uint32_t sBl = sbase + 2 * TILE_BYTES;

        #pragma unroll
        for (int ks = 0; ks < 2; ks++) {
            const uint32_t kByte = (uint32_t)(ks * 32);

            uint32_t rA[4][4], rBh[4][2], rBl[4][2];
            // A fragments: 4x ldmatrix.x4 (one 16x16 frag per m-tile)
            #pragma unroll
            for (int mt = 0; mt < 4; mt++)
                LDMATRIX_X4(rA[mt][0], rA[mt][1], rA[mt][2], rA[mt][3],
                            sA + aByte + kByte + (uint32_t)(mt * 16 * ROWB));
            // Bhi fragments: 2x ldmatrix.x4 (n-tile pairs {0,1},{2,3})
            LDMATRIX_X4(rBh[0][0], rBh[0][1], rBh[1][0], rBh[1][1], sBh + bByte + kByte);
            LDMATRIX_X4(rBh[2][0], rBh[2][1], rBh[3][0], rBh[3][1],
                        sBh + bByte + kByte + (uint32_t)(16 * ROWB));
            // Blo fragments
            LDMATRIX_X4(rBl[0][0], rBl[0][1], rBl[1][0], rBl[1][1], sBl + bByte + kByte);
            LDMATRIX_X4(rBl[2][0], rBl[2][1], rBl[3][0], rBl[3][1],
                        sBl + bByte + kByte + (uint32_t)(16 * ROWB));

            // 32 back-to-back HMMAs
            #pragma unroll
            for (int mt = 0; mt < 4; mt++)
                #pragma unroll
                for (int nt = 0; nt < 4; nt++)
                    mma_f16(acc[mt][nt], rA[mt], rBh[nt]);
            #pragma unroll
            for (int mt = 0; mt < 4; mt++)
                #pragma unroll
                for (int nt = 0; nt < 4; nt++)
                    mma_f16(acc[mt][nt], rA[mt], rBl[nt]);
        }
        __syncthreads();
    }

    // ---- epilogue: fp32 stores ----
    #pragma unroll
    for (int mt = 0; mt < 4; mt++) {
        const int row = m0 + warp_m * 64 + mt * 16 + g;
        #pragma unroll
        for (int nt = 0; nt < 4; nt++) {
            const int col = n0 + warp_n * 32 + nt * 8 + cp2;
            *reinterpret_cast<float2*>(C + (size_t)row * Ntot + col) =
                make_float2(acc[mt][nt][0], acc[mt][nt][1]);
            *reinterpret_cast<float2*>(C + (size_t)(row + 8) * Ntot + col) =
                make_float2(acc[mt][nt][2], acc[mt][nt][3]);
        }
    }
}

// ---------------------------------------------------------------------------
// Local attention: one block per row, one warp per head. fp32 math, fp16 out.
// ---------------------------------------------------------------------------
__global__ __launch_bounds__(256)
void local_attn_kernel(const float* __restrict__ qkv,
                       const float* __restrict__ pos_bias,
                       __half* __restrict__ out)
{
    const int m    = blockIdx.x;
    const int seq  = m & (S_LEN - 1);
    const int base = m - seq;
    const int h    = threadIdx.x >> 5;
    const int lane = threadIdx.x & 31;

    const float* qp = qkv + (size_t)m * N_QKV + h * DK;
    const float q0 = qp[lane]      * 0.125f;
    const float q1 = qp[lane + 32] * 0.125f;

    const float* bias_row = pos_bias + ((size_t)h * S_LEN + seq) * KSIZE;

    float logit[KSIZE];
    #pragma unroll
    for (int j = 0; j < KSIZE; j++) {
        const int s2 = seq + j - PAD;
        float p = 0.0f;
        if (s2 >= 0 && s2 < S_LEN) {
            const float* kp = qkv + (size_t)(base + s2) * N_QKV + D_MODEL + h * DK;
            p = q0 * kp[lane] + q1 * kp[lane + 32];
        }
        #pragma unroll
        for (int off = 16; off > 0; off >>= 1)
            p += __shfl_xor_sync(0xffffffffu, p, off);
        logit[j] = p + bias_row[j];
    }

    float mx = logit[0];
    #pragma unroll
    for (int j = 1; j < KSIZE; j++) mx = fmaxf(mx, logit[j]);
    float e[KSIZE], sum = 0.0f;
    #pragma unroll
    for (int j = 0; j < KSIZE; j++) { e[j] = __expf(logit[j] - mx); sum += e[j]; }
    const float inv = 1.0f / sum;

    float o0 = 0.0f, o1 = 0.0f;
    #pragma unroll
    for (int j = 0; j < KSIZE; j++) {
        const int s2 = seq + j - PAD;
        if (s2 >= 0 && s2 < S_LEN) {
            const float* vp = qkv + (size_t)(base + s2) * N_QKV + 2 * D_MODEL + h * DK;
            const float a = e[j] * inv;
            o0 += a * vp[lane];
            o1 += a * vp[lane + 32];
        }
    }

    const size_t ob = (size_t)m * D_MODEL + h * DK;
    out[ob + lane]      = __float2half_rn(o0);
    out[ob + lane + 32] = __float2half_rn(o1);
}

// ---------------------------------------------------------------------------
// Launch
// ---------------------------------------------------------------------------
extern "C" void kernel_launch(void* const* d_in, const int* in_sizes, int n_in,
                              void* d_out, int out_size)
{
    const float* inputs   = (const float*)d_in[0];
    const float* pos_bias = (const float*)d_in[1];
    const float* W_qkv    = (const float*)d_in[2];
    const float* W_out    = (const float*)d_in[3];
    float*       out      = (float*)d_out;

    float *qkv; __half *a16, *att, *wqhi, *wqlo, *wohi, *wolo;
    cudaGetSymbolAddress((void**)&qkv,  g_qkv);
    cudaGetSymbolAddress((void**)&a16,  g_a);
    cudaGetSymbolAddress((void**)&att,  g_att);
    cudaGetSymbolAddress((void**)&wqhi, g_wqhi);
    cudaGetSymbolAddress((void**)&wqlo, g_wqlo);
    cudaGetSymbolAddress((void**)&wohi, g_wohi);
    cudaGetSymbolAddress((void**)&wolo, g_wolo);

    cudaFuncSetAttribute(gemm_mma_kernel,
                         cudaFuncAttributeMaxDynamicSharedMemorySize, SMEM_TOTAL);

    // 0) Conversions
    convert_act_kernel<<<(M_ROWS * K_DIM / 4) / 256, 256>>>(inputs, a16);
    convert_w_kernel<<<(N_QKV * K_DIM) / 256, 256>>>(W_qkv, wqhi, wqlo, K_DIM, N_QKV);
    convert_w_kernel<<<(D_MODEL * K_DIM) / 256, 256>>>(W_out, wohi, wolo, K_DIM, D_MODEL);

    // 1) QKV projection: [32768,512] @ [512,1536]
    {
        dim3 grid(N_QKV / BN, M_ROWS / BM);
        gemm_mma_kernel<<<grid, 256, SMEM_TOTAL>>>(a16, wqhi, wqlo, qkv, N_QKV);
    }
    // 2) Local windowed attention
    local_attn_kernel<<<M_ROWS, 256>>>(qkv, pos_bias, att);
    // 3) Output projection: [32768,512] @ [512,512]
    {
        dim3 grid(D_MODEL / BN, M_ROWS / BM);
        gemm_mma_kernel<<<grid, 256, SMEM_TOTAL>>>(att, wohi, wolo, out, D_MODEL);
    }
}

// round 7
// speedup vs baseline: 5.6059x; 1.5782x over previous
#include <cuda_runtime.h>
#include <cuda_fp16.h>
#include <cstdint>

// ---------------- problem constants ----------------
#define HEADS   8
#define DK      64
#define KSIZE   7
#define PAD     3
#define S_LEN   256
#define D_MODEL 512
#define M_ROWS  32768            // B*HW*S
#define N_QKV   1536
#define K_DIM   512

// ---------------- GEMM tiling ----------------
#define BM 128
#define BN 128
#define BK 64
#define NCHUNK (K_DIM / BK)      // 8
#define RB 144                   // padded row stride bytes (64 halfs + 8 pad)
#define TILE_BYTES (BM * RB)             // 18432
#define BUF_BYTES  (2 * TILE_BYTES)      // A | B = 36864
#define NSTAGE 3
#define SMEM_TOTAL (NSTAGE * BUF_BYTES)  // 110592

// ---------------- scratch (__device__ globals; no allocs allowed) ----------
__device__ float   g_qkv[(size_t)M_ROWS * N_QKV];      // 192 MiB
__device__ __half  g_a  [(size_t)M_ROWS * K_DIM];      // fp16 activations
__device__ __half  g_att[(size_t)M_ROWS * D_MODEL];    // fp16 attention out
__device__ __half  g_wq [(size_t)N_QKV * K_DIM];       // fp16 W_qkv^T
__device__ __half  g_wo [(size_t)D_MODEL * K_DIM];     // fp16 W_out^T

// ---------------- helpers ----------------
__device__ __forceinline__ uint32_t smem_u32(const void* p) {
    uint32_t a;
    asm("{ .reg .u64 t; cvta.to.shared.u64 t, %1; cvt.u32.u64 %0, t; }" : "=r"(a) : "l"(p));
    return a;
}
#define CP_ASYNC16(sa, gp) \
    asm volatile("cp.async.cg.shared.global [%0], [%1], 16;" :: "r"(sa), "l"(gp) : "memory")
#define CP_COMMIT() asm volatile("cp.async.commit_group;" ::: "memory")
#define CP_WAIT1()  asm volatile("cp.async.wait_group 1;" ::: "memory")
#define CP_WAIT0()  asm volatile("cp.async.wait_group 0;" ::: "memory")

#define LDMATRIX_X4(r0, r1, r2, r3, addr) \
    asm volatile("ldmatrix.sync.aligned.m8n8.x4.shared.b16 {%0,%1,%2,%3}, [%4];" \
        : "=r"(r0), "=r"(r1), "=r"(r2), "=r"(r3) : "r"(addr))

__device__ __forceinline__ void mma_f16(float* d, const uint32_t* a, const uint32_t* b) {
    asm volatile(
        "mma.sync.aligned.m16n8k16.row.col.f32.f16.f16.f32 "
        "{%0,%1,%2,%3}, {%4,%5,%6,%7}, {%8,%9}, {%0,%1,%2,%3};"
        : "+f"(d[0]), "+f"(d[1]), "+f"(d[2]), "+f"(d[3])
        : "r"(a[0]), "r"(a[1]), "r"(a[2]), "r"(a[3]), "r"(b[0]), "r"(b[1]));
}

// ---------------------------------------------------------------------------
// Conversions
// ---------------------------------------------------------------------------
__global__ __launch_bounds__(256)
void convert_act_kernel(const float* __restrict__ in, __half* __restrict__ out)
{
    size_t i = ((size_t)blockIdx.x * 256 + threadIdx.x) * 4;
    float4 v = *reinterpret_cast<const float4*>(in + i);
    *reinterpret_cast<__half2*>(out + i)     = __floats2half2_rn(v.x, v.y);
    *reinterpret_cast<__half2*>(out + i + 2) = __floats2half2_rn(v.z, v.w);
}

// W [Kd, Nd] row-major fp32 -> Wt [Nd, Kd] fp16 (K-contiguous)
__global__ __launch_bounds__(256)
void convert_w_kernel(const float* __restrict__ W, __half* __restrict__ Wt,
                      int Kd, int Nd)
{
    size_t idx = (size_t)blockIdx.x * 256 + threadIdx.x;
    int n = (int)(idx / Kd);
    int k = (int)(idx % Kd);
    Wt[idx] = __float2half_rn(W[(size_t)k * Nd + n]);
}

// ---------------------------------------------------------------------------
// fp16 GEMM:  C[M, Ntot] = A[M,512] @ B^T   (B stored [Ntot, 512] K-contig)
// CTA 128x128, BK=64, 8 warps (warp tile 64x32), 3-stage cp.async ring,
// ONE __syncthreads per chunk, ldmatrix.x4 fragments, 2 CTAs/SM.
// ---------------------------------------------------------------------------
__global__ __launch_bounds__(256, 2)
void gemm_mma_kernel(const __half* __restrict__ A,
                     const __half* __restrict__ B,
                     float* __restrict__ C, int Ntot)
{
    extern __shared__ char smem[];
    const uint32_t sb = smem_u32(smem);
    const int tid = threadIdx.x;
    const int wid = tid >> 5;
    const int lid = tid & 31;
    const int warp_m = wid & 1;          // 0..1 -> 64 rows
    const int warp_n = wid >> 1;         // 0..3 -> 32 cols
    const int g   = lid >> 2;            // 0..7
    const int cp2 = (lid & 3) * 2;

    const int m0 = blockIdx.y * BM;
    const int n0 = blockIdx.x * BN;

    // ldmatrix per-lane byte offsets (within a tile)
    const uint32_t aByte = (uint32_t)((warp_m * 64 + (lid & 15)) * RB + (lid >> 4) * 16);
    const int bmi = lid >> 3;
    const uint32_t bByte = (uint32_t)((warp_n * 32 + (bmi >> 1) * 8 + (lid & 7)) * RB
                                      + (bmi & 1) * 16);

    const __half* baseptr[2] = { A + (size_t)m0 * K_DIM, B + (size_t)n0 * K_DIM };

    // chunk c -> stage s. 2 tiles x 128 rows x 8 quads = 2048 cp.async, 8/thread
    auto load_chunk = [&](int c, int s) {
        const int kof = c * BK;
        const uint32_t sbase = sb + s * BUF_BYTES;
        #pragma unroll
        for (int i = 0; i < 8; i++) {
            const int u    = tid + i * 256;          // 0..2047
            const int t    = u >> 10;                // tile 0..1
            const int v    = u & 1023;
            const int row  = v >> 3;
            const int quad = v & 7;
            const uint32_t sa = sbase + t * TILE_BYTES + row * RB + quad * 16;
            const __half* gp = baseptr[t] + (size_t)row * K_DIM + kof + quad * 8;
            CP_ASYNC16(sa, gp);
        }
    };

    float acc[4][4][4];
    #pragma unroll
    for (int i = 0; i < 4; i++)
        #pragma unroll
        for (int j = 0; j < 4; j++)
            #pragma unroll
            for (int q = 0; q < 4; q++) acc[i][j][q] = 0.0f;

    load_chunk(0, 0); CP_COMMIT();
    load_chunk(1, 1); CP_COMMIT();

    for (int c = 0; c < NCHUNK; c++) {
        if (c < NCHUNK - 1) CP_WAIT1(); else CP_WAIT0();
        __syncthreads();

        const uint32_t sbase = sb + (c % NSTAGE) * BUF_BYTES;
        const uint32_t sA = sbase;
        const uint32_t sB = sbase + TILE_BYTES;

        #pragma unroll
        for (int ks = 0; ks < 4; ks++) {
            const uint32_t kByte = (uint32_t)(ks * 32);

            uint32_t rA[4][4], rB[4][2];
            #pragma unroll
            for (int mt = 0; mt < 4; mt++)
                LDMATRIX_X4(rA[mt][0], rA[mt][1], rA[mt][2], rA[mt][3],
                            sA + aByte + kByte + (uint32_t)(mt * 16 * RB));
            LDMATRIX_X4(rB[0][0], rB[0][1], rB[1][0], rB[1][1], sB + bByte + kByte);
            LDMATRIX_X4(rB[2][0], rB[2][1], rB[3][0], rB[3][1],
                        sB + bByte + kByte + (uint32_t)(16 * RB));

            #pragma unroll
            for (int mt = 0; mt < 4; mt++)
                #pragma unroll
                for (int nt = 0; nt < 4; nt++)
                    mma_f16(acc[mt][nt], rA[mt], rB[nt]);
        }

        // Load chunk c+2 into stage (c+2)%3 = (c-1)%3: every warp that reaches
        // here passed this iteration's barrier, so all warps finished computing
        // stage (c-1)%3 in the previous iteration. Race-free with one BAR.
        if (c + 2 < NCHUNK) {
            load_chunk(c + 2, (c + 2) % NSTAGE);
            CP_COMMIT();
        }
    }

    // ---- epilogue: fp32 stores ----
    #pragma unroll
    for (int mt = 0; mt < 4; mt++) {
        const int row = m0 + warp_m * 64 + mt * 16 + g;
        #pragma unroll
        for (int nt = 0; nt < 4; nt++) {
            const int col = n0 + warp_n * 32 + nt * 8 + cp2;
            *reinterpret_cast<float2*>(C + (size_t)row * Ntot + col) =
                make_float2(acc[mt][nt][0], acc[mt][nt][1]);
            *reinterpret_cast<float2*>(C + (size_t)(row + 8) * Ntot + col) =
                make_float2(acc[mt][nt][2], acc[mt][nt][3]);
        }
    }
}

// ---------------------------------------------------------------------------
// Local attention: one block per row, one warp per head. fp32 math, fp16 out.
// ---------------------------------------------------------------------------
__global__ __launch_bounds__(256)
void local_attn_kernel(const float* __restrict__ qkv,
                       const float* __restrict__ pos_bias,
                       __half* __restrict__ out)
{
    const int m    = blockIdx.x;
    const int seq  = m & (S_LEN - 1);
    const int base = m - seq;
    const int h    = threadIdx.x >> 5;
    const int lane = threadIdx.x & 31;

    const float* qp = qkv + (size_t)m * N_QKV + h * DK;
    const float q0 = qp[lane]      * 0.125f;
    const float q1 = qp[lane + 32] * 0.125f;

    const float* bias_row = pos_bias + ((size_t)h * S_LEN + seq) * KSIZE;

    float logit[KSIZE];
    #pragma unroll
    for (int j = 0; j < KSIZE; j++) {
        const int s2 = seq + j - PAD;
        float p = 0.0f;
        if (s2 >= 0 && s2 < S_LEN) {
            const float* kp = qkv + (size_t)(base + s2) * N_QKV + D_MODEL + h * DK;
            p = q0 * kp[lane] + q1 * kp[lane + 32];
        }
        #pragma unroll
        for (int off = 16; off > 0; off >>= 1)
            p += __shfl_xor_sync(0xffffffffu, p, off);
        logit[j] = p + bias_row[j];
    }

    float mx = logit[0];
    #pragma unroll
    for (int j = 1; j < KSIZE; j++) mx = fmaxf(mx, logit[j]);
    float e[KSIZE], sum = 0.0f;
    #pragma unroll
    for (int j = 0; j < KSIZE; j++) { e[j] = __expf(logit[j] - mx); sum += e[j]; }
    const float inv = 1.0f / sum;

    float o0 = 0.0f, o1 = 0.0f;
    #pragma unroll
    for (int j = 0; j < KSIZE; j++) {
        const int s2 = seq + j - PAD;
        if (s2 >= 0 && s2 < S_LEN) {
            const float* vp = qkv + (size_t)(base + s2) * N_QKV + 2 * D_MODEL + h * DK;
            const float a = e[j] * inv;
            o0 += a * vp[lane];
            o1 += a * vp[lane + 32];
        }
    }

    const size_t ob = (size_t)m * D_MODEL + h * DK;
    out[ob + lane]      = __float2half_rn(o0);
    out[ob + lane + 32] = __float2half_rn(o1);
}

// ---------------------------------------------------------------------------
// Launch
// ---------------------------------------------------------------------------
extern "C" void kernel_launch(void* const* d_in, const int* in_sizes, int n_in,
                              void* d_out, int out_size)
{
    const float* inputs   = (const float*)d_in[0];
    const float* pos_bias = (const float*)d_in[1];
    const float* W_qkv    = (const float*)d_in[2];
    const float* W_out    = (const float*)d_in[3];
    float*       out      = (float*)d_out;

    float *qkv; __half *a16, *att, *wq, *wo;
    cudaGetSymbolAddress((void**)&qkv, g_qkv);
    cudaGetSymbolAddress((void**)&a16, g_a);
    cudaGetSymbolAddress((void**)&att, g_att);
    cudaGetSymbolAddress((void**)&wq,  g_wq);
    cudaGetSymbolAddress((void**)&wo,  g_wo);

    cudaFuncSetAttribute(gemm_mma_kernel,
                         cudaFuncAttributeMaxDynamicSharedMemorySize, SMEM_TOTAL);

    // 0) Conversions
    convert_act_kernel<<<(M_ROWS * K_DIM / 4) / 256, 256>>>(inputs, a16);
    convert_w_kernel<<<(N_QKV * K_DIM) / 256, 256>>>(W_qkv, wq, K_DIM, N_QKV);
    convert_w_kernel<<<(D_MODEL * K_DIM) / 256, 256>>>(W_out, wo, K_DIM, D_MODEL);

    // 1) QKV projection: [32768,512] @ [512,1536]
    {
        dim3 grid(N_QKV / BN, M_ROWS / BM);
        gemm_mma_kernel<<<grid, 256, SMEM_TOTAL>>>(a16, wq, qkv, N_QKV);
    }
    // 2) Local windowed attention
    local_attn_kernel<<<M_ROWS, 256>>>(qkv, pos_bias, att);
    // 3) Output projection: [32768,512] @ [512,512]
    {
        dim3 grid(D_MODEL / BN, M_ROWS / BM);
        gemm_mma_kernel<<<grid, 256, SMEM_TOTAL>>>(att, wo, out, D_MODEL);
    }
}